// round 15
// baseline (speedup 1.0000x reference)
#include <cuda_runtime.h>
#include <cuda_fp16.h>
#include <cstdint>

#define B_DIM 2048
#define M_DIM 64
#define F_DIM 512
#define U_DIM 512
#define LDX (M_DIM * F_DIM)
#define LDO (M_DIM * U_DIM)

#define BM 256
#define BN 128
#define BK 64
#define THREADS 256            // 8 warps: 4 (M) x 2 (N), warp tile 64x64
#define KITERS (F_DIM / BK)    // 8

#define ROWB 144                             // bytes per smem row (64 halves + 8 pad)
#define A_TILE_BYTES (256 * ROWB)            // 36864
#define B_TILE_BYTES (128 * ROWB)            // 18432
#define STAGE_BYTES (A_TILE_BYTES + B_TILE_BYTES)   // 55296
#define STAGES 3
#define DYN_SMEM (STAGES * STAGE_BYTES)      // 165888 B -> 1 CTA/SM

__device__ __half g_Wh[(size_t)M_DIM * F_DIM * U_DIM];   // W^T fp16: [m][u][k]
__device__ __half g_Xh[(size_t)B_DIM * M_DIM * F_DIM];   // x fp16:  [b][m][f]

// ---------------- helpers ----------------
static __device__ __forceinline__ uint32_t cvta_smem(const void* p) {
    uint32_t a;
    asm("{ .reg .u64 t; cvta.to.shared.u64 t, %1; cvt.u32.u64 %0, t; }" : "=r"(a) : "l"(p));
    return a;
}
static __device__ __forceinline__ void cp_async16(uint32_t smem_addr, const void* gptr) {
    asm volatile("cp.async.cg.shared.global [%0], [%1], 16;" :: "r"(smem_addr), "l"(gptr) : "memory");
}
static __device__ __forceinline__ void cp_commit() {
    asm volatile("cp.async.commit_group;" ::: "memory");
}
template <int N>
static __device__ __forceinline__ void cp_wait() {
    asm volatile("cp.async.wait_group %0;" :: "n"(N) : "memory");
}
static __device__ __forceinline__ void ldsm_x4(uint32_t addr, uint32_t* r) {
    asm volatile("ldmatrix.sync.aligned.m8n8.x4.shared.b16 {%0,%1,%2,%3}, [%4];"
                 : "=r"(r[0]), "=r"(r[1]), "=r"(r[2]), "=r"(r[3]) : "r"(addr));
}
static __device__ __forceinline__ void mma_f16(float* c, const uint32_t* a, const uint32_t* b) {
    asm volatile(
        "mma.sync.aligned.m16n8k16.row.col.f32.f16.f16.f32 "
        "{%0,%1,%2,%3}, {%4,%5,%6,%7}, {%8,%9}, {%0,%1,%2,%3};"
        : "+f"(c[0]), "+f"(c[1]), "+f"(c[2]), "+f"(c[3])
        : "r"(a[0]), "r"(a[1]), "r"(a[2]), "r"(a[3]), "r"(b[0]), "r"(b[1]));
}

// ---------------- prep 1: x -> fp16 (same layout) ----------------
__global__ void convert_x_kernel(const float4* __restrict__ xin) {
    const size_t idx = (size_t)blockIdx.x * blockDim.x + threadIdx.x;  // 8 floats each
    float4 v0 = xin[idx * 2], v1 = xin[idx * 2 + 1];
    __half2 h0 = __floats2half2_rn(v0.x, v0.y);
    __half2 h1 = __floats2half2_rn(v0.z, v0.w);
    __half2 h2 = __floats2half2_rn(v1.x, v1.y);
    __half2 h3 = __floats2half2_rn(v1.z, v1.w);
    uint4 o;
    o.x = *(uint32_t*)&h0; o.y = *(uint32_t*)&h1;
    o.z = *(uint32_t*)&h2; o.w = *(uint32_t*)&h3;
    reinterpret_cast<uint4*>(g_Xh)[idx] = o;
}

// ---------------- prep 2: W transpose + fp16: g_Wh[m][u][k] = (half)W[m][k][u] ----------------
__global__ void transpose_W_kernel(const float* __restrict__ W) {
    __shared__ float t[32][33];
    const int m = blockIdx.z;
    const int u0 = blockIdx.x * 32, k0 = blockIdx.y * 32;
    const int tx = threadIdx.x, ty = threadIdx.y;
    const float* Wm = W + (size_t)m * F_DIM * U_DIM;
    __half* Wtm = g_Wh + (size_t)m * F_DIM * U_DIM;
#pragma unroll
    for (int i = 0; i < 32; i += 8)
        t[ty + i][tx] = Wm[(size_t)(k0 + ty + i) * U_DIM + u0 + tx];
    __syncthreads();
#pragma unroll
    for (int i = 0; i < 32; i += 8)
        Wtm[(size_t)(u0 + ty + i) * F_DIM + k0 + tx] = __float2half_rn(t[tx][ty + i]);
}

// ---------------- main GEMM: fp16 mma.sync, 64x64 warp tiles, frag double-buffer ----------------
__global__ __launch_bounds__(THREADS, 1)
void pd_mma_f16(const float* __restrict__ bias,
                float* __restrict__ out) {
    extern __shared__ __align__(16) char smem[];
    const uint32_t smemAddr = cvta_smem(smem);

    const int tid  = threadIdx.x;
    const int wid  = tid >> 5;
    const int lane = tid & 31;
    const int warpM = wid >> 1;         // 0..3 -> 64-row slice of 256
    const int warpN = wid & 1;          // 0..1 -> 64-col slice of 128
    const int g = lane >> 2;            // groupID
    const int t = lane & 3;             // thread-in-group
    const int quad = lane >> 3;         // ldmatrix address quad
    const int rl   = lane & 7;
    const int rot  = (wid & 1) * 2;     // ks rotation: desync LDSM bursts

    const int bn = blockIdx.x, bm = blockIdx.y, m = blockIdx.z;
    const int rowBase = bm * BM;
    const int colBase = bn * BN;

    const __half* Xm  = g_Xh + (size_t)m * F_DIM;
    const __half* Wtm = g_Wh + (size_t)m * F_DIM * U_DIM;

    // ---- A staging: 256 rows x 8 chunks(16B) = 2048; 8/thread, r steps 32 ----
    const int aR0 = tid >> 3, aC = tid & 7;
    const __half* aFillSrc = Xm + (size_t)(rowBase + aR0) * LDX + aC * 8;
    const uint32_t aFillDst = (uint32_t)(aR0 * ROWB + aC * 16);
    // ---- B staging: 128 rows x 8 chunks(16B) = 1024; 4/thread, r steps 32 ----
    const __half* bFillSrc = Wtm + (size_t)(colBase + aR0) * F_DIM + aC * 8;
    const uint32_t bFillDst = aFillDst + A_TILE_BYTES;

    auto issue_A_half = [&](uint32_t stageOff, int k0, int h) {   // h = 0 or 1 (4 chunks)
#pragma unroll
        for (int j = 0; j < 4; ++j) {
            int jj = h * 4 + j;
            cp_async16(smemAddr + stageOff + aFillDst + jj * 32 * ROWB,
                       aFillSrc + (size_t)jj * 32 * LDX + k0);
        }
    };
    auto issue_B = [&](uint32_t stageOff, int k0) {               // + commit (1 group/stage)
#pragma unroll
        for (int j = 0; j < 4; ++j)
            cp_async16(smemAddr + stageOff + bFillDst + j * 32 * ROWB,
                       bFillSrc + (size_t)j * 32 * F_DIM + k0);
        cp_commit();
    };

    // ---- ldmatrix per-lane offsets ----
    const uint32_t aLaneOff =
        (uint32_t)((warpM * 64 + (quad & 1) * 8 + rl) * ROWB + (quad >> 1) * 16);
    const uint32_t bLaneOff =
        (uint32_t)((warpN * 64 + (quad >> 1) * 8 + rl) * ROWB + (quad & 1) * 16) + A_TILE_BYTES;

    float acc[4][8][4];
#pragma unroll
    for (int mi = 0; mi < 4; ++mi)
#pragma unroll
        for (int ni = 0; ni < 8; ++ni)
#pragma unroll
            for (int c = 0; c < 4; ++c) acc[mi][ni][c] = 0.0f;

    // ---- prologue: stages 0,1 in flight ----
    issue_A_half(0, 0, 0); issue_A_half(0, 0, 1); issue_B(0, 0);
    issue_A_half(STAGE_BYTES, BK, 0); issue_A_half(STAGE_BYTES, BK, 1); issue_B(STAGE_BYTES, BK);

    uint32_t compOff  = 0;
    uint32_t issueOff = 2 * STAGE_BYTES;

    // double-buffered fragments
    uint32_t af[2][4][4], bf[2][4][4];

    for (int it = 0; it < KITERS; ++it) {
        // Pending groups: stages it, it+1. wait<1> -> stage `it` arrived.
        cp_wait<1>();
        // Barrier: stage it visible to all; all warps done computing it-1
        // (its buffer (it+2)%3 is re-filled below, after this barrier).
        __syncthreads();

        const uint32_t aA = smemAddr + compOff + aLaneOff;
        const uint32_t bA = smemAddr + compOff + bLaneOff;

        const bool fill = (it + 2 < KITERS);
        const int fillK = (it + 2) * BK;

        // preload fragments for kk=0 into buffer 0
        {
            const uint32_t ko = (uint32_t)(((0 + rot) & 3) * 32);
#pragma unroll
            for (int mi = 0; mi < 4; ++mi) ldsm_x4(aA + mi * 16 * ROWB + ko, af[0][mi]);
#pragma unroll
            for (int p = 0; p < 4; ++p)    ldsm_x4(bA + p * 16 * ROWB + ko, bf[0][p]);
        }

#pragma unroll
        for (int kk = 0; kk < 4; ++kk) {
            const int cur = kk & 1, nxt = cur ^ 1;

            // prefetch fragments for kk+1 (in flight during this chunk's MMAs)
            if (kk < 3) {
                const uint32_t ko = (uint32_t)(((kk + 1 + rot) & 3) * 32);
#pragma unroll
                for (int mi = 0; mi < 4; ++mi) ldsm_x4(aA + mi * 16 * ROWB + ko, af[nxt][mi]);
#pragma unroll
                for (int p = 0; p < 4; ++p)    ldsm_x4(bA + p * 16 * ROWB + ko, bf[nxt][p]);
            }

            // cp.async issue for stage it+2, spread across kk phases
            if (kk == 0) {
                if (fill) issue_A_half(issueOff, fillK, 0);
            } else if (kk == 1) {
                if (fill) issue_A_half(issueOff, fillK, 1);
            } else if (kk == 2) {
                if (fill) issue_B(issueOff, fillK);
                else      cp_commit();               // keep group accounting aligned
            }

            // 32 MMAs on current buffer (fragments loaded in previous phase)
#pragma unroll
            for (int p = 0; p < 4; ++p) {
#pragma unroll
                for (int mi = 0; mi < 4; ++mi) {
                    mma_f16(acc[mi][2 * p],     af[cur][mi], &bf[cur][p][0]);
                    mma_f16(acc[mi][2 * p + 1], af[cur][mi], &bf[cur][p][2]);
                }
            }
        }

        compOff += STAGE_BYTES;  if (compOff  == DYN_SMEM) compOff  = 0;
        issueOff += STAGE_BYTES; if (issueOff == DYN_SMEM) issueOff = 0;
    }

    // ---------------- epilogue: bias + relu + store ----------------
    const float* bm_bias = bias + (size_t)m * U_DIM + colBase + warpN * 64;
#pragma unroll
    for (int mi = 0; mi < 4; ++mi) {
        const int r0 = rowBase + warpM * 64 + mi * 16 + g;
        float* o0 = out + (size_t)r0 * LDO + (size_t)m * U_DIM + colBase + warpN * 64;
        float* o1 = o0 + (size_t)8 * LDO;
#pragma unroll
        for (int ni = 0; ni < 8; ++ni) {
            const int c = ni * 8 + t * 2;
            const float b0 = bm_bias[c], b1 = bm_bias[c + 1];
            float2 v0, v1;
            v0.x = fmaxf(acc[mi][ni][0] + b0, 0.0f);
            v0.y = fmaxf(acc[mi][ni][1] + b1, 0.0f);
            v1.x = fmaxf(acc[mi][ni][2] + b0, 0.0f);
            v1.y = fmaxf(acc[mi][ni][3] + b1, 0.0f);
            *(float2*)(o0 + c) = v0;
            *(float2*)(o1 + c) = v1;
        }
    }
}

// ---------------- launch ----------------
extern "C" void kernel_launch(void* const* d_in, const int* in_sizes, int n_in,
                              void* d_out, int out_size) {
    const float* x    = (const float*)d_in[0];
    const float* W    = (const float*)d_in[1];
    const float* bias = (const float*)d_in[2];
    float* out        = (float*)d_out;

    convert_x_kernel<<<32768, 256>>>((const float4*)x);
    dim3 tg(U_DIM / 32, F_DIM / 32, M_DIM);   // (16,16,64)
    transpose_W_kernel<<<tg, dim3(32, 8)>>>(W);

    cudaFuncSetAttribute(pd_mma_f16, cudaFuncAttributeMaxDynamicSharedMemorySize, DYN_SMEM);
    dim3 grid(U_DIM / BN, B_DIM / BM, M_DIM);  // (4,8,64) = 2048 CTAs
    pd_mma_f16<<<grid, THREADS, DYN_SMEM>>>(bias, out);
}

// round 16
// speedup vs baseline: 1.1074x; 1.1074x over previous
#include <cuda_runtime.h>
#include <cuda_fp16.h>
#include <cstdint>

#define B_DIM 2048
#define M_DIM 64
#define F_DIM 512
#define U_DIM 512
#define LDX (M_DIM * F_DIM)
#define LDO (M_DIM * U_DIM)

#define BM 128
#define BN 128
#define BK 64
#define THREADS 128            // 4 warps: 2 (M) x 2 (N), warp tile 64x64
#define KITERS (F_DIM / BK)    // 8

#define ROWB 144                             // bytes per smem row (64 halves + 8 pad)
#define A_TILE_BYTES (128 * ROWB)            // 18432
#define B_TILE_BYTES (128 * ROWB)            // 18432
#define STAGE_BYTES (A_TILE_BYTES + B_TILE_BYTES)   // 36864
#define STAGES 3
#define DYN_SMEM (STAGES * STAGE_BYTES)      // 110592 B/CTA -> 2 CTAs/SM (216 KB)

__device__ __half g_Wh[(size_t)M_DIM * F_DIM * U_DIM];   // W^T fp16: [m][u][k]
__device__ __half g_Xh[(size_t)B_DIM * M_DIM * F_DIM];   // x fp16:  [b][m][f]

// ---------------- helpers ----------------
static __device__ __forceinline__ uint32_t cvta_smem(const void* p) {
    uint32_t a;
    asm("{ .reg .u64 t; cvta.to.shared.u64 t, %1; cvt.u32.u64 %0, t; }" : "=r"(a) : "l"(p));
    return a;
}
static __device__ __forceinline__ void cp_async16(uint32_t smem_addr, const void* gptr) {
    asm volatile("cp.async.cg.shared.global [%0], [%1], 16;" :: "r"(smem_addr), "l"(gptr) : "memory");
}
static __device__ __forceinline__ void cp_commit() {
    asm volatile("cp.async.commit_group;" ::: "memory");
}
template <int N>
static __device__ __forceinline__ void cp_wait() {
    asm volatile("cp.async.wait_group %0;" :: "n"(N) : "memory");
}
static __device__ __forceinline__ void ldsm_x4(uint32_t addr, uint32_t* r) {
    asm volatile("ldmatrix.sync.aligned.m8n8.x4.shared.b16 {%0,%1,%2,%3}, [%4];"
                 : "=r"(r[0]), "=r"(r[1]), "=r"(r[2]), "=r"(r[3]) : "r"(addr));
}
static __device__ __forceinline__ void mma_f16(float* c, const uint32_t* a, const uint32_t* b) {
    asm volatile(
        "mma.sync.aligned.m16n8k16.row.col.f32.f16.f16.f32 "
        "{%0,%1,%2,%3}, {%4,%5,%6,%7}, {%8,%9}, {%0,%1,%2,%3};"
        : "+f"(c[0]), "+f"(c[1]), "+f"(c[2]), "+f"(c[3])
        : "r"(a[0]), "r"(a[1]), "r"(a[2]), "r"(a[3]), "r"(b[0]), "r"(b[1]));
}

// ---------------- prep 1: x -> fp16 (same layout) ----------------
__global__ void convert_x_kernel(const float4* __restrict__ xin) {
    const size_t idx = (size_t)blockIdx.x * blockDim.x + threadIdx.x;  // 8 floats each
    float4 v0 = xin[idx * 2], v1 = xin[idx * 2 + 1];
    __half2 h0 = __floats2half2_rn(v0.x, v0.y);
    __half2 h1 = __floats2half2_rn(v0.z, v0.w);
    __half2 h2 = __floats2half2_rn(v1.x, v1.y);
    __half2 h3 = __floats2half2_rn(v1.z, v1.w);
    uint4 o;
    o.x = *(uint32_t*)&h0; o.y = *(uint32_t*)&h1;
    o.z = *(uint32_t*)&h2; o.w = *(uint32_t*)&h3;
    reinterpret_cast<uint4*>(g_Xh)[idx] = o;
}

// ---------------- prep 2: W transpose + fp16: g_Wh[m][u][k] = (half)W[m][k][u] ----------------
__global__ void transpose_W_kernel(const float* __restrict__ W) {
    __shared__ float t[32][33];
    const int m = blockIdx.z;
    const int u0 = blockIdx.x * 32, k0 = blockIdx.y * 32;
    const int tx = threadIdx.x, ty = threadIdx.y;
    const float* Wm = W + (size_t)m * F_DIM * U_DIM;
    __half* Wtm = g_Wh + (size_t)m * F_DIM * U_DIM;
#pragma unroll
    for (int i = 0; i < 32; i += 8)
        t[ty + i][tx] = Wm[(size_t)(k0 + ty + i) * U_DIM + u0 + tx];
    __syncthreads();
#pragma unroll
    for (int i = 0; i < 32; i += 8)
        Wtm[(size_t)(u0 + ty + i) * F_DIM + k0 + tx] = __float2half_rn(t[tx][ty + i]);
}

// ---------------- main GEMM: 128-thread CTAs, 64x64 warp tiles, 2 CTAs/SM ----------------
__global__ __launch_bounds__(THREADS, 2)
void pd_mma_f16(const float* __restrict__ bias,
                float* __restrict__ out) {
    extern __shared__ __align__(16) char smem[];
    const uint32_t smemAddr = cvta_smem(smem);

    const int tid  = threadIdx.x;
    const int wid  = tid >> 5;          // 0..3
    const int lane = tid & 31;
    const int warpM = wid >> 1;         // 0..1 -> 64-row slice of 128
    const int warpN = wid & 1;          // 0..1 -> 64-col slice of 128
    const int g = lane >> 2;            // groupID
    const int t = lane & 3;             // thread-in-group
    const int quad = lane >> 3;         // ldmatrix address quad
    const int rl   = lane & 7;
    const int rot  = (wid & 1) * 2;     // ks rotation: desync LDSM bursts

    const int bn = blockIdx.x, bm = blockIdx.y, m = blockIdx.z;
    const int rowBase = bm * BM;
    const int colBase = bn * BN;

    const __half* Xm  = g_Xh + (size_t)m * F_DIM;
    const __half* Wtm = g_Wh + (size_t)m * F_DIM * U_DIM;

    // ---- staging: per tile 128 rows x 8 chunks(16B) = 1024 chunks; 8/thread, r steps 16 ----
    const int aR0 = tid >> 3, aC = tid & 7;       // aR0: 0..15
    const __half* aFillSrc = Xm + (size_t)(rowBase + aR0) * LDX + aC * 8;
    const uint32_t aFillDst = (uint32_t)(aR0 * ROWB + aC * 16);
    const __half* bFillSrc = Wtm + (size_t)(colBase + aR0) * F_DIM + aC * 8;
    const uint32_t bFillDst = aFillDst + A_TILE_BYTES;

    auto issue_A_half = [&](uint32_t stageOff, int k0, int h) {   // h=0/1: rows [h*64, h*64+64)
#pragma unroll
        for (int j = 0; j < 4; ++j) {
            int jj = h * 4 + j;
            cp_async16(smemAddr + stageOff + aFillDst + jj * 16 * ROWB,
                       aFillSrc + (size_t)jj * 16 * LDX + k0);
        }
    };
    auto issue_B_half = [&](uint32_t stageOff, int k0, int h) {
#pragma unroll
        for (int j = 0; j < 4; ++j) {
            int jj = h * 4 + j;
            cp_async16(smemAddr + stageOff + bFillDst + jj * 16 * ROWB,
                       bFillSrc + (size_t)jj * 16 * F_DIM + k0);
        }
        if (h == 1) cp_commit();        // 1 group per stage
    };

    // ---- ldmatrix per-lane offsets ----
    const uint32_t aLaneOff =
        (uint32_t)((warpM * 64 + (quad & 1) * 8 + rl) * ROWB + (quad >> 1) * 16);
    const uint32_t bLaneOff =
        (uint32_t)((warpN * 64 + (quad >> 1) * 8 + rl) * ROWB + (quad & 1) * 16) + A_TILE_BYTES;

    float acc[4][8][4];
#pragma unroll
    for (int mi = 0; mi < 4; ++mi)
#pragma unroll
        for (int ni = 0; ni < 8; ++ni)
#pragma unroll
            for (int c = 0; c < 4; ++c) acc[mi][ni][c] = 0.0f;

    // ---- prologue: stages 0,1 in flight ----
    issue_A_half(0, 0, 0); issue_A_half(0, 0, 1);
    issue_B_half(0, 0, 0); issue_B_half(0, 0, 1);
    issue_A_half(STAGE_BYTES, BK, 0); issue_A_half(STAGE_BYTES, BK, 1);
    issue_B_half(STAGE_BYTES, BK, 0); issue_B_half(STAGE_BYTES, BK, 1);

    uint32_t compOff  = 0;
    uint32_t issueOff = 2 * STAGE_BYTES;

    for (int it = 0; it < KITERS; ++it) {
        // Pending groups: stages it, it+1. wait<1> -> stage `it` arrived.
        cp_wait<1>();
        // Barrier: stage it visible to all; all warps done computing it-1
        // (its buffer (it+2)%3 is re-filled below, after this barrier).
        __syncthreads();

        const uint32_t aA = smemAddr + compOff + aLaneOff;
        const uint32_t bA = smemAddr + compOff + bLaneOff;

        const bool fill = (it + 2 < KITERS);
        const int fillK = (it + 2) * BK;

#pragma unroll
        for (int kk = 0; kk < 4; ++kk) {
            const int ks = (kk + rot) & 3;           // warp-parity rotated k16-chunk
            const uint32_t ko = (uint32_t)(ks * 32); // 16 halves = 32 B

            uint32_t af[4][4], bf[4][4];
#pragma unroll
            for (int mi = 0; mi < 4; ++mi)
                ldsm_x4(aA + mi * 16 * ROWB + ko, af[mi]);
            ldsm_x4(bA + ko,             bf[0]);     // n-groups 0,1
            ldsm_x4(bA + 16 * ROWB + ko, bf[1]);     // n-groups 2,3
#pragma unroll
            for (int p = 0; p < 2; ++p) {
#pragma unroll
                for (int mi = 0; mi < 4; ++mi) {
                    mma_f16(acc[mi][2 * p],     af[mi], &bf[p][0]);
                    mma_f16(acc[mi][2 * p + 1], af[mi], &bf[p][2]);
                }
            }
            ldsm_x4(bA + 32 * ROWB + ko, bf[2]);     // n-groups 4,5
            ldsm_x4(bA + 48 * ROWB + ko, bf[3]);     // n-groups 6,7

            // spread cp.async issue for stage it+2 across kk phases
            if (kk == 0) {
                if (fill) issue_A_half(issueOff, fillK, 0);
            } else if (kk == 1) {
                if (fill) issue_A_half(issueOff, fillK, 1);
            } else if (kk == 2) {
                if (fill) issue_B_half(issueOff, fillK, 0);
            } else {
                if (fill) issue_B_half(issueOff, fillK, 1);
                else      cp_commit();               // keep group accounting aligned
            }

#pragma unroll
            for (int p = 2; p < 4; ++p) {
#pragma unroll
                for (int mi = 0; mi < 4; ++mi) {
                    mma_f16(acc[mi][2 * p],     af[mi], &bf[p][0]);
                    mma_f16(acc[mi][2 * p + 1], af[mi], &bf[p][2]);
                }
            }
        }

        compOff += STAGE_BYTES;  if (compOff  == DYN_SMEM) compOff  = 0;
        issueOff += STAGE_BYTES; if (issueOff == DYN_SMEM) issueOff = 0;
    }

    // ---------------- epilogue: bias + relu + store ----------------
    const float* bm_bias = bias + (size_t)m * U_DIM + colBase + warpN * 64;
#pragma unroll
    for (int mi = 0; mi < 4; ++mi) {
        const int r0 = rowBase + warpM * 64 + mi * 16 + g;
        float* o0 = out + (size_t)r0 * LDO + (size_t)m * U_DIM + colBase + warpN * 64;
        float* o1 = o0 + (size_t)8 * LDO;
#pragma unroll
        for (int ni = 0; ni < 8; ++ni) {
            const int c = ni * 8 + t * 2;
            const float b0 = bm_bias[c], b1 = bm_bias[c + 1];
            float2 v0, v1;
            v0.x = fmaxf(acc[mi][ni][0] + b0, 0.0f);
            v0.y = fmaxf(acc[mi][ni][1] + b1, 0.0f);
            v1.x = fmaxf(acc[mi][ni][2] + b0, 0.0f);
            v1.y = fmaxf(acc[mi][ni][3] + b1, 0.0f);
            *(float2*)(o0 + c) = v0;
            *(float2*)(o1 + c) = v1;
        }
    }
}

// ---------------- launch ----------------
extern "C" void kernel_launch(void* const* d_in, const int* in_sizes, int n_in,
                              void* d_out, int out_size) {
    const float* x    = (const float*)d_in[0];
    const float* W    = (const float*)d_in[1];
    const float* bias = (const float*)d_in[2];
    float* out        = (float*)d_out;

    convert_x_kernel<<<32768, 256>>>((const float4*)x);
    dim3 tg(U_DIM / 32, F_DIM / 32, M_DIM);   // (16,16,64)
    transpose_W_kernel<<<tg, dim3(32, 8)>>>(W);

    cudaFuncSetAttribute(pd_mma_f16, cudaFuncAttributeMaxDynamicSharedMemorySize, DYN_SMEM);
    dim3 grid(U_DIM / BN, B_DIM / BM, M_DIM);  // (4,16,64) = 4096 CTAs
    pd_mma_f16<<<grid, THREADS, DYN_SMEM>>>(bias, out);
}